// round 2
// baseline (speedup 1.0000x reference)
#include <cuda_runtime.h>
#include <cstdint>

// Problem constants
#define NN      65536
#define CIN_A   64
#define COUT    128
#define KK_A    27

// ---------------- scratch (no allocations allowed) ----------------
__device__ float g_xT  [NN * CIN_A];          // x node-major [N][64]
__device__ float g_wTa [KK_A * CIN_A * COUT]; // [k][c][o]
__device__ float g_wTb [KK_A * COUT * COUT];  // [k][c][o]
__device__ float g_wTs [CIN_A * COUT];        // [c][o]
__device__ float g_ya  [NN * COUT];           // conv_a out, node-major
__device__ float g_c1  [NN * COUT];           // relu(bn(ya))
__device__ float g_yb  [NN * COUT];
__device__ float g_ys  [NN * COUT];
__device__ int   g_self[NN];
__device__ float g_psumA[256 * 128], g_psqA[256 * 128];
__device__ float g_psumB[256 * 128], g_psqB[256 * 128];
__device__ float g_psumS[256 * 128], g_psqS[256 * 128];
__device__ float g_scA[128], g_biA[128];
__device__ float g_scB[128], g_biB[128];
__device__ float g_scS[128], g_biS[128];

// ---------------- f32x2 helpers ----------------
__device__ __forceinline__ unsigned long long pack2(float lo, float hi) {
    unsigned long long r;
    asm("mov.b64 %0, {%1, %2};" : "=l"(r) : "f"(lo), "f"(hi));
    return r;
}
__device__ __forceinline__ void unpack2(unsigned long long v, float& lo, float& hi) {
    asm("mov.b64 {%0, %1}, %2;" : "=f"(lo), "=f"(hi) : "l"(v));
}
__device__ __forceinline__ unsigned long long fma2(unsigned long long a,
                                                   unsigned long long b,
                                                   unsigned long long c) {
    unsigned long long d;
    asm("fma.rn.f32x2 %0, %1, %2, %3;" : "=l"(d) : "l"(a), "l"(b), "l"(c));
    return d;
}

// ---------------- prep kernels ----------------

// data [64][N] -> xT [N][64]
__global__ void k_transpose_x(const float* __restrict__ src, float* __restrict__ dst) {
    __shared__ float tile[32][33];
    int n0 = blockIdx.x * 32, c0 = blockIdx.y * 32;
    int tx = threadIdx.x, ty = threadIdx.y; // 32 x 8
    #pragma unroll
    for (int i = 0; i < 32; i += 8)
        tile[ty + i][tx] = src[(size_t)(c0 + ty + i) * NN + n0 + tx];
    __syncthreads();
    #pragma unroll
    for (int i = 0; i < 32; i += 8)
        dst[(size_t)(n0 + ty + i) * 64 + c0 + tx] = tile[tx][ty + i];
}

// w [o][c][k] -> wt [k][c][o]
__global__ void k_wprep(const float* __restrict__ w, float* __restrict__ wt,
                        int cin, int kk) {
    int idx = blockIdx.x * blockDim.x + threadIdx.x;
    int total = COUT * cin * kk;
    if (idx >= total) return;
    int k = idx % kk;
    int c = (idx / kk) % cin;
    int o = idx / (kk * cin);
    wt[((size_t)k * cin + c) * COUT + o] = w[idx];
}

__global__ void k_iota(int* __restrict__ p) {
    int i = blockIdx.x * blockDim.x + threadIdx.x;
    if (i < NN) p[i] = i;
}

// ---------------- implicit-GEMM conv (f32x2 microkernel) ----------------
// y[n][o] = sum_{k<KNB, c<CIN} wT[k][c][o] * src[neigh[n*KNB+k]][c]
// tile: 128 nodes x 128 outputs, 256 threads, 8(out) x 8(node) microtiles
// with node-dim pairs packed for FFMA2.
template <int CIN, int KNB>
__global__ void __launch_bounds__(256, 2)
k_conv(const float* __restrict__ src,   // [N][CIN] node-major
       const int*   __restrict__ nbr,   // [N][KNB]
       const float* __restrict__ wT,    // [KNB][CIN][128]
       float*       __restrict__ y)     // [N][128] node-major
{
    __shared__ float ws[32][128];          // [c][o]
    __shared__ float gs[32][132];          // [c][n] (+pad)
    __shared__ int   nb[128 * KNB];        // all neighbor ids for this tile

    const int n0 = blockIdx.x * 128;
    const int t  = threadIdx.x;            // 0..255
    const int tx = t & 15;                 // node dir
    const int ty = t >> 4;                 // out dir

    // preload ALL neighbor indices (coalesced)
    #pragma unroll
    for (int idx = t; idx < 128 * KNB; idx += 256)
        nb[idx] = nbr[(size_t)n0 * KNB + idx];
    // no sync needed yet; first use is after first __syncthreads below

    unsigned long long acc[8][4];          // [out i][node pair jp]
    #pragma unroll
    for (int i = 0; i < 8; ++i)
        #pragma unroll
        for (int jp = 0; jp < 4; ++jp) acc[i][jp] = 0ull;

    __syncthreads();                       // nb visible

    for (int k = 0; k < KNB; ++k) {
        #pragma unroll
        for (int cc = 0; cc < CIN; cc += 32) {
            // weights chunk: wT[k][cc..cc+31][0..127] contiguous -> 1024 float4
            {
                const float4* wsrc = (const float4*)(wT + ((size_t)k * CIN + cc) * COUT);
                float4* wdst = (float4*)&ws[0][0];
                #pragma unroll
                for (int i = 0; i < 4; ++i)
                    wdst[t + 256 * i] = wsrc[t + 256 * i];
            }
            // gather chunk: node j channels [cc, cc+32), transposed into gs[c][j]
            {
                int j    = t >> 1;
                int part = t & 1;
                const float4* gsrc =
                    (const float4*)(src + (size_t)nb[j * KNB + k] * CIN + cc) + part * 4;
                #pragma unroll
                for (int i = 0; i < 4; ++i) {
                    float4 v = gsrc[i];
                    int c = part * 16 + i * 4;
                    gs[c + 0][j] = v.x;
                    gs[c + 1][j] = v.y;
                    gs[c + 2][j] = v.z;
                    gs[c + 3][j] = v.w;
                }
            }
            __syncthreads();

            #pragma unroll
            for (int c = 0; c < 32; ++c) {
                float4 w0 = *(const float4*)&ws[c][ty * 8];
                float4 w1 = *(const float4*)&ws[c][ty * 8 + 4];
                union { float4 f4; unsigned long long u2[2]; } ga, gb;
                ga.f4 = *(const float4*)&gs[c][tx * 8];
                gb.f4 = *(const float4*)&gs[c][tx * 8 + 4];
                unsigned long long gp0 = ga.u2[0], gp1 = ga.u2[1];
                unsigned long long gp2 = gb.u2[0], gp3 = gb.u2[1];

                unsigned long long wp[8];
                wp[0] = pack2(w0.x, w0.x); wp[1] = pack2(w0.y, w0.y);
                wp[2] = pack2(w0.z, w0.z); wp[3] = pack2(w0.w, w0.w);
                wp[4] = pack2(w1.x, w1.x); wp[5] = pack2(w1.y, w1.y);
                wp[6] = pack2(w1.z, w1.z); wp[7] = pack2(w1.w, w1.w);

                #pragma unroll
                for (int i = 0; i < 8; ++i) {
                    acc[i][0] = fma2(wp[i], gp0, acc[i][0]);
                    acc[i][1] = fma2(wp[i], gp1, acc[i][1]);
                    acc[i][2] = fma2(wp[i], gp2, acc[i][2]);
                    acc[i][3] = fma2(wp[i], gp3, acc[i][3]);
                }
            }
            __syncthreads();
        }
    }

    // write y[n0 + tx*8 + j][ty*8 + i], j = jp*2 + half
    #pragma unroll
    for (int jp = 0; jp < 4; ++jp) {
        float lo[8], hi[8];
        #pragma unroll
        for (int i = 0; i < 8; ++i) unpack2(acc[i][jp], lo[i], hi[i]);
        float4* d0 = (float4*)(y + (size_t)(n0 + tx * 8 + jp * 2 + 0) * COUT + ty * 8);
        float4* d1 = (float4*)(y + (size_t)(n0 + tx * 8 + jp * 2 + 1) * COUT + ty * 8);
        d0[0] = make_float4(lo[0], lo[1], lo[2], lo[3]);
        d0[1] = make_float4(lo[4], lo[5], lo[6], lo[7]);
        d1[0] = make_float4(hi[0], hi[1], hi[2], hi[3]);
        d1[1] = make_float4(hi[4], hi[5], hi[6], hi[7]);
    }
}

// ---------------- BN stats (deterministic two-level) ----------------
__global__ void k_reduce(const float* __restrict__ y,
                         float* __restrict__ psum, float* __restrict__ psq) {
    int b = blockIdx.x, t = threadIdx.x;
    int c = t & 127, h = t >> 7;
    float s = 0.f, q = 0.f;
    const float* p = y + ((size_t)b * 256 + h * 128) * 128 + c;
    #pragma unroll 4
    for (int i = 0; i < 128; ++i) {
        float v = p[(size_t)i * 128];
        s += v;
        q += v * v;
    }
    __shared__ float sh[256], sh2[256];
    sh[t] = s; sh2[t] = q;
    __syncthreads();
    if (h == 0) {
        psum[b * 128 + c] = sh[c] + sh[128 + c];
        psq [b * 128 + c] = sh2[c] + sh2[128 + c];
    }
}

__global__ void k_finalize(const float* __restrict__ psum, const float* __restrict__ psq,
                           const float* __restrict__ gamma, const float* __restrict__ beta,
                           float* __restrict__ scale, float* __restrict__ bias) {
    int c = threadIdx.x; // 128
    double s = 0.0, q = 0.0;
    for (int i = 0; i < 256; ++i) {
        s += (double)psum[i * 128 + c];
        q += (double)psq [i * 128 + c];
    }
    double mu  = s / (double)NN;
    double var = q / (double)NN - mu * mu;
    float sc = gamma[c] * rsqrtf((float)var + 1e-3f);
    scale[c] = sc;
    bias[c]  = beta[c] - sc * (float)mu;
}

// c1 = relu(scale*y + bias), elementwise, float4
__global__ void k_bnrelu(const float* __restrict__ y,
                         const float* __restrict__ scale, const float* __restrict__ bias,
                         float* __restrict__ c1) {
    size_t idx = (size_t)blockIdx.x * blockDim.x + threadIdx.x; // over N*128/4
    float4 v = ((const float4*)y)[idx];
    int c = (int)((idx * 4) & 127);
    v.x = fmaxf(scale[c + 0] * v.x + bias[c + 0], 0.f);
    v.y = fmaxf(scale[c + 1] * v.y + bias[c + 1], 0.f);
    v.z = fmaxf(scale[c + 2] * v.z + bias[c + 2], 0.f);
    v.w = fmaxf(scale[c + 3] * v.w + bias[c + 3], 0.f);
    ((float4*)c1)[idx] = v;
}

// out[o][n] = relu(scB*yb[n][o]+biB + scS*ys[n][o]+biS)  (node-major -> chan-major)
__global__ void k_final(const float* __restrict__ yb, const float* __restrict__ ys,
                        const float* __restrict__ scB, const float* __restrict__ biB,
                        const float* __restrict__ scS, const float* __restrict__ biS,
                        float* __restrict__ out) {
    __shared__ float tile[32][33];
    int n0 = blockIdx.x * 32, o0 = blockIdx.y * 32;
    int tx = threadIdx.x, ty = threadIdx.y; // 32 x 8
    #pragma unroll
    for (int i = 0; i < 32; i += 8) {
        int n = n0 + ty + i, o = o0 + tx;
        size_t off = (size_t)n * 128 + o;
        float v = scB[o] * yb[off] + biB[o] + scS[o] * ys[off] + biS[o];
        tile[ty + i][tx] = fmaxf(v, 0.f);
    }
    __syncthreads();
    #pragma unroll
    for (int i = 0; i < 32; i += 8)
        out[(size_t)(o0 + ty + i) * NN + n0 + tx] = tile[tx][ty + i];
}

// ---------------- launch ----------------
template <typename T>
static T* sym_addr(const void* sym) {
    void* p = nullptr;
    cudaGetSymbolAddress(&p, sym);
    return (T*)p;
}

extern "C" void kernel_launch(void* const* d_in, const int* in_sizes, int n_in,
                              void* d_out, int out_size) {
    const float* data    = (const float*)d_in[0];
    const int*   neigh   = (const int*)  d_in[1];
    const float* w_a     = (const float*)d_in[2];
    const float* w_b     = (const float*)d_in[3];
    const float* w_skip  = (const float*)d_in[4];
    const float* gamma_a = (const float*)d_in[5];
    const float* beta_a  = (const float*)d_in[6];
    const float* gamma_b = (const float*)d_in[7];
    const float* beta_b  = (const float*)d_in[8];
    const float* gamma_s = (const float*)d_in[9];
    const float* beta_s  = (const float*)d_in[10];
    float* out = (float*)d_out;

    float* xT  = sym_addr<float>(g_xT);
    float* wTa = sym_addr<float>(g_wTa);
    float* wTb = sym_addr<float>(g_wTb);
    float* wTs = sym_addr<float>(g_wTs);
    float* ya  = sym_addr<float>(g_ya);
    float* c1  = sym_addr<float>(g_c1);
    float* yb  = sym_addr<float>(g_yb);
    float* ys  = sym_addr<float>(g_ys);
    int*   self= sym_addr<int>(g_self);
    float* psA = sym_addr<float>(g_psumA); float* pqA = sym_addr<float>(g_psqA);
    float* psB = sym_addr<float>(g_psumB); float* pqB = sym_addr<float>(g_psqB);
    float* psS = sym_addr<float>(g_psumS); float* pqS = sym_addr<float>(g_psqS);
    float* scA = sym_addr<float>(g_scA);   float* biA = sym_addr<float>(g_biA);
    float* scB = sym_addr<float>(g_scB);   float* biB = sym_addr<float>(g_biB);
    float* scS = sym_addr<float>(g_scS);   float* biS = sym_addr<float>(g_biS);

    // prep
    k_transpose_x<<<dim3(NN / 32, 2), dim3(32, 8)>>>(data, xT);
    k_wprep<<<(COUT * CIN_A * KK_A + 255) / 256, 256>>>(w_a, wTa, CIN_A, KK_A);
    k_wprep<<<(COUT * COUT * KK_A + 255) / 256, 256>>>(w_b, wTb, COUT, KK_A);
    k_wprep<<<(COUT * CIN_A * 1 + 255) / 256, 256>>>(w_skip, wTs, CIN_A, 1);
    k_iota<<<NN / 256, 256>>>(self);

    // conv_a -> BN stats -> relu(bn)
    k_conv<64, 27><<<NN / 128, 256>>>(xT, neigh, wTa, ya);
    k_reduce<<<256, 256>>>(ya, psA, pqA);
    k_finalize<<<1, 128>>>(psA, pqA, gamma_a, beta_a, scA, biA);
    k_bnrelu<<<(NN * 128 / 4) / 256, 256>>>(ya, scA, biA, c1);

    // conv_b and skip GEMM
    k_conv<128, 27><<<NN / 128, 256>>>(c1, neigh, wTb, yb);
    k_conv<64, 1><<<NN / 128, 256>>>(xT, self, wTs, ys);

    // BN stats for b and skip
    k_reduce<<<256, 256>>>(yb, psB, pqB);
    k_finalize<<<1, 128>>>(psB, pqB, gamma_b, beta_b, scB, biB);
    k_reduce<<<256, 256>>>(ys, psS, pqS);
    k_finalize<<<1, 128>>>(psS, pqS, gamma_s, beta_s, scS, biS);

    // fused add + relu + transpose to [128][N]
    k_final<<<dim3(NN / 32, 4), dim3(32, 8)>>>(yb, ys, scB, biB, scS, biS, out);
}

// round 10
// speedup vs baseline: 2.2720x; 2.2720x over previous
#include <cuda_runtime.h>
#include <cstdint>

#define NN      65536
#define CIN_A   64
#define COUT    128
#define KK_A    27

// ---------------- scratch ----------------
__device__ float g_xT  [NN * CIN_A];            // x node-major [N][64], tf32-rounded
__device__ float g_wTa [KK_A * CIN_A * COUT];   // per-chunk [o][c] images (tf32)
__device__ float g_wTb [KK_A * COUT * COUT];
__device__ float g_wTs [CIN_A * COUT];
__device__ float g_ya  [NN * COUT];
__device__ float g_c1  [NN * COUT];             // tf32-rounded
__device__ float g_yb  [NN * COUT];
__device__ float g_ys  [NN * COUT];
__device__ float g_psumA[256 * 128], g_psqA[256 * 128];
__device__ float g_psumB[256 * 128], g_psqB[256 * 128];
__device__ float g_psumS[256 * 128], g_psqS[256 * 128];
__device__ float g_scA[128], g_biA[128];
__device__ float g_scB[128], g_biB[128];
__device__ float g_scS[128], g_biS[128];

// ---------------- helpers ----------------
__device__ __forceinline__ float to_tf32(float x) {
    uint32_t u;
    asm("cvt.rna.tf32.f32 %0, %1;" : "=r"(u) : "f"(x));
    return __uint_as_float(u);
}

// D += A(16x8,row) * B(8x8,col)  tf32 inputs, fp32 accum
__device__ __forceinline__ void mma8(float* d, const float* a, const float* b) {
    asm volatile(
        "mma.sync.aligned.m16n8k8.row.col.f32.tf32.tf32.f32 "
        "{%0,%1,%2,%3}, {%4,%5,%6,%7}, {%8,%9}, {%0,%1,%2,%3};"
        : "+f"(d[0]), "+f"(d[1]), "+f"(d[2]), "+f"(d[3])
        : "r"(__float_as_uint(a[0])), "r"(__float_as_uint(a[1])),
          "r"(__float_as_uint(a[2])), "r"(__float_as_uint(a[3])),
          "r"(__float_as_uint(b[0])), "r"(__float_as_uint(b[1])));
}

// ---------------- prep kernels ----------------

// data [64][N] -> xT [N][64], tf32-rounded
__global__ void k_transpose_x(const float* __restrict__ src, float* __restrict__ dst) {
    __shared__ float tile[32][33];
    int n0 = blockIdx.x * 32, c0 = blockIdx.y * 32;
    int tx = threadIdx.x, ty = threadIdx.y; // 32 x 8
    #pragma unroll
    for (int i = 0; i < 32; i += 8)
        tile[ty + i][tx] = src[(size_t)(c0 + ty + i) * NN + n0 + tx];
    __syncthreads();
    #pragma unroll
    for (int i = 0; i < 32; i += 8)
        dst[(size_t)(n0 + ty + i) * 64 + c0 + tx] = to_tf32(tile[tx][ty + i]);
}

// w [o][c][k] -> chunk images: wt[chunk][o*32 + (c%32)], chunk = k*(cin/32)+c/32
__global__ void k_wprep(const float* __restrict__ w, float* __restrict__ wt,
                        int cin, int kk) {
    int idx = blockIdx.x * blockDim.x + threadIdx.x;
    int total = COUT * cin * kk;
    if (idx >= total) return;
    int k = idx % kk;
    int c = (idx / kk) % cin;
    int o = idx / (kk * cin);
    int chunk = k * (cin >> 5) + (c >> 5);
    wt[(size_t)chunk * 4096 + o * 32 + (c & 31)] = to_tf32(w[idx]);
}

// ---------------- mma.sync implicit-GEMM conv ----------------
// y[n][o] = sum_{k,c} w[o][c][k] * src[neigh[n][k]][c]
// CTA: 128 nodes x 128 outs, 8 warps in 2(M) x 4(N), warp tile m64 n32.
// SMEM rows padded to 36 floats -> conflict-free fragment loads.
template <int CIN, int KNB, bool SELF>
__global__ void __launch_bounds__(256, 2)
k_conv_mma(const float* __restrict__ src,   // [N][CIN] tf32
           const int*   __restrict__ nbr,   // [N][KNB] (unused if SELF)
           const float* __restrict__ wC,    // chunk images [Q][128*32]
           float*       __restrict__ y)     // [N][128]
{
    extern __shared__ char smem[];
    constexpr int NCH = CIN / 32;
    constexpr int Q   = KNB * NCH;
    constexpr int NBB = SELF ? 0 : 128 * KNB * 4;
    constexpr int OFF_A = (NBB + 15) & ~15;          // bytes
    constexpr int BUF   = 128 * 36;                  // floats per buffer
    // layout: [nb][A0][A1][B0][B1]

    int* nb = (int*)smem;
    float* Abase = (float*)(smem + OFF_A);
    float* Bbase = Abase + 2 * BUF;

    const int n0   = blockIdx.x * 128;
    const int t    = threadIdx.x;
    const int warp = t >> 5, lane = t & 31;
    const int wm   = warp & 1, wn = warp >> 1;
    const int r    = lane >> 2, cl = lane & 3;

    if (!SELF) {
        for (int i = t; i < 128 * KNB; i += 256)
            nb[i] = nbr[(size_t)n0 * KNB + i];
    }
    __syncthreads();

    float acc[4][4][4];
    #pragma unroll
    for (int i = 0; i < 4; ++i)
        #pragma unroll
        for (int j = 0; j < 4; ++j)
            #pragma unroll
            for (int e = 0; e < 4; ++e) acc[i][j][e] = 0.f;

    const int gnode = t >> 1, ghalf = t & 1;

    for (int q = 0; q < Q; ++q) {
        const int k  = q / NCH;
        const int cc = (q % NCH) * 32;
        float* As = Abase + (q & 1) * BUF;
        float* Bs = Bbase + (q & 1) * BUF;

        // gather A: 128 nodes x 32 ch
        {
            int idx = SELF ? (n0 + gnode) : nb[gnode * KNB + k];
            const float4* g = (const float4*)(src + (size_t)idx * CIN + cc + ghalf * 16);
            float4 v0 = g[0], v1 = g[1], v2 = g[2], v3 = g[3];
            float* dst = As + gnode * 36 + ghalf * 16;
            *(float4*)(dst + 0)  = v0;
            *(float4*)(dst + 4)  = v1;
            *(float4*)(dst + 8)  = v2;
            *(float4*)(dst + 12) = v3;
        }
        // copy B image: 128 outs x 32 ch (1024 float4)
        {
            const float4* bsrc = (const float4*)(wC + (size_t)q * 4096);
            #pragma unroll
            for (int i = 0; i < 4; ++i) {
                int p = t + 256 * i;
                float4 v = bsrc[p];
                *(float4*)(Bs + (p >> 3) * 36 + (p & 7) * 4) = v;
            }
        }
        __syncthreads();

        // compute: 4 k-steps of m16n8k8
        #pragma unroll
        for (int ks = 0; ks < 4; ++ks) {
            const int k0 = ks * 8;
            float a[4][4], b[4][2];
            #pragma unroll
            for (int i = 0; i < 4; ++i) {
                const float* base = As + (wm * 64 + i * 16 + r) * 36 + k0 + cl;
                a[i][0] = base[0];
                a[i][1] = base[8 * 36];
                a[i][2] = base[4];
                a[i][3] = base[8 * 36 + 4];
            }
            #pragma unroll
            for (int j = 0; j < 4; ++j) {
                const float* base = Bs + (wn * 32 + j * 8 + r) * 36 + k0 + cl;
                b[j][0] = base[0];
                b[j][1] = base[4];
            }
            #pragma unroll
            for (int i = 0; i < 4; ++i)
                #pragma unroll
                for (int j = 0; j < 4; ++j)
                    mma8(acc[i][j], a[i], b[j]);
        }
        __syncthreads();
    }

    // epilogue: d0,d1 at (row, 2c),(row, 2c+1); d2,d3 at (row+8, ...)
    #pragma unroll
    for (int i = 0; i < 4; ++i) {
        int row = n0 + wm * 64 + i * 16 + r;
        #pragma unroll
        for (int j = 0; j < 4; ++j) {
            int col = wn * 32 + j * 8 + cl * 2;
            *(float2*)(y + (size_t)row * 128 + col) =
                make_float2(acc[i][j][0], acc[i][j][1]);
            *(float2*)(y + (size_t)(row + 8) * 128 + col) =
                make_float2(acc[i][j][2], acc[i][j][3]);
        }
    }
}

// ---------------- BN stats (deterministic two-level) ----------------
__global__ void k_reduce(const float* __restrict__ y,
                         float* __restrict__ psum, float* __restrict__ psq) {
    int b = blockIdx.x, t = threadIdx.x;
    int c = t & 127, h = t >> 7;
    float s = 0.f, q = 0.f;
    const float* p = y + ((size_t)b * 256 + h * 128) * 128 + c;
    #pragma unroll 4
    for (int i = 0; i < 128; ++i) {
        float v = p[(size_t)i * 128];
        s += v;
        q += v * v;
    }
    __shared__ float sh[256], sh2[256];
    sh[t] = s; sh2[t] = q;
    __syncthreads();
    if (h == 0) {
        psum[b * 128 + c] = sh[c] + sh[128 + c];
        psq [b * 128 + c] = sh2[c] + sh2[128 + c];
    }
}

__global__ void k_finalize(const float* __restrict__ psum, const float* __restrict__ psq,
                           const float* __restrict__ gamma, const float* __restrict__ beta,
                           float* __restrict__ scale, float* __restrict__ bias) {
    int c = threadIdx.x; // 128
    double s = 0.0, q = 0.0;
    for (int i = 0; i < 256; ++i) {
        s += (double)psum[i * 128 + c];
        q += (double)psq [i * 128 + c];
    }
    double mu  = s / (double)NN;
    double var = q / (double)NN - mu * mu;
    float sc = gamma[c] * rsqrtf((float)var + 1e-3f);
    scale[c] = sc;
    bias[c]  = beta[c] - sc * (float)mu;
}

// c1 = tf32(relu(scale*y + bias))
__global__ void k_bnrelu(const float* __restrict__ y,
                         const float* __restrict__ scale, const float* __restrict__ bias,
                         float* __restrict__ c1) {
    size_t idx = (size_t)blockIdx.x * blockDim.x + threadIdx.x;
    float4 v = ((const float4*)y)[idx];
    int c = (int)((idx * 4) & 127);
    v.x = to_tf32(fmaxf(scale[c + 0] * v.x + bias[c + 0], 0.f));
    v.y = to_tf32(fmaxf(scale[c + 1] * v.y + bias[c + 1], 0.f));
    v.z = to_tf32(fmaxf(scale[c + 2] * v.z + bias[c + 2], 0.f));
    v.w = to_tf32(fmaxf(scale[c + 3] * v.w + bias[c + 3], 0.f));
    ((float4*)c1)[idx] = v;
}

// out[o][n] = relu(scB*yb[n][o]+biB + scS*ys[n][o]+biS)
__global__ void k_final(const float* __restrict__ yb, const float* __restrict__ ys,
                        const float* __restrict__ scB, const float* __restrict__ biB,
                        const float* __restrict__ scS, const float* __restrict__ biS,
                        float* __restrict__ out) {
    __shared__ float tile[32][33];
    int n0 = blockIdx.x * 32, o0 = blockIdx.y * 32;
    int tx = threadIdx.x, ty = threadIdx.y; // 32 x 8
    #pragma unroll
    for (int i = 0; i < 32; i += 8) {
        int n = n0 + ty + i, o = o0 + tx;
        size_t off = (size_t)n * 128 + o;
        float v = scB[o] * yb[off] + biB[o] + scS[o] * ys[off] + biS[o];
        tile[ty + i][tx] = fmaxf(v, 0.f);
    }
    __syncthreads();
    #pragma unroll
    for (int i = 0; i < 32; i += 8)
        out[(size_t)(o0 + ty + i) * NN + n0 + tx] = tile[tx][ty + i];
}

// ---------------- launch ----------------
template <typename T>
static T* sym_addr(const void* sym) {
    void* p = nullptr;
    cudaGetSymbolAddress(&p, sym);
    return (T*)p;
}

// conv smem: nb(128*27*4=13824, 16B-aligned) + 4 bufs * 18432 = 87552
// skip smem: 4 bufs * 18432 = 73728
enum { SMEM_CONV = 87552, SMEM_SKIP = 73728 };

extern "C" void kernel_launch(void* const* d_in, const int* in_sizes, int n_in,
                              void* d_out, int out_size) {
    const float* data    = (const float*)d_in[0];
    const int*   neigh   = (const int*)  d_in[1];
    const float* w_a     = (const float*)d_in[2];
    const float* w_b     = (const float*)d_in[3];
    const float* w_skip  = (const float*)d_in[4];
    const float* gamma_a = (const float*)d_in[5];
    const float* beta_a  = (const float*)d_in[6];
    const float* gamma_b = (const float*)d_in[7];
    const float* beta_b  = (const float*)d_in[8];
    const float* gamma_s = (const float*)d_in[9];
    const float* beta_s  = (const float*)d_in[10];
    float* out = (float*)d_out;

    float* xT  = sym_addr<float>(g_xT);
    float* wTa = sym_addr<float>(g_wTa);
    float* wTb = sym_addr<float>(g_wTb);
    float* wTs = sym_addr<float>(g_wTs);
    float* ya  = sym_addr<float>(g_ya);
    float* c1  = sym_addr<float>(g_c1);
    float* yb  = sym_addr<float>(g_yb);
    float* ys  = sym_addr<float>(g_ys);
    float* psA = sym_addr<float>(g_psumA); float* pqA = sym_addr<float>(g_psqA);
    float* psB = sym_addr<float>(g_psumB); float* pqB = sym_addr<float>(g_psqB);
    float* psS = sym_addr<float>(g_psumS); float* pqS = sym_addr<float>(g_psqS);
    float* scA = sym_addr<float>(g_scA);   float* biA = sym_addr<float>(g_biA);
    float* scB = sym_addr<float>(g_scB);   float* biB = sym_addr<float>(g_biB);
    float* scS = sym_addr<float>(g_scS);   float* biS = sym_addr<float>(g_biS);

    cudaFuncSetAttribute(k_conv_mma<64, 27, false>,
                         cudaFuncAttributeMaxDynamicSharedMemorySize, SMEM_CONV);
    cudaFuncSetAttribute(k_conv_mma<128, 27, false>,
                         cudaFuncAttributeMaxDynamicSharedMemorySize, SMEM_CONV);
    cudaFuncSetAttribute(k_conv_mma<64, 1, true>,
                         cudaFuncAttributeMaxDynamicSharedMemorySize, SMEM_SKIP);

    // prep
    k_transpose_x<<<dim3(NN / 32, 2), dim3(32, 8)>>>(data, xT);
    k_wprep<<<(COUT * CIN_A * KK_A + 255) / 256, 256>>>(w_a, wTa, CIN_A, KK_A);
    k_wprep<<<(COUT * COUT * KK_A + 255) / 256, 256>>>(w_b, wTb, COUT, KK_A);
    k_wprep<<<(COUT * CIN_A + 255) / 256, 256>>>(w_skip, wTs, CIN_A, 1);

    // conv_a -> BN -> relu
    k_conv_mma<64, 27, false><<<NN / 128, 256, SMEM_CONV>>>(xT, neigh, wTa, ya);
    k_reduce<<<256, 256>>>(ya, psA, pqA);
    k_finalize<<<1, 128>>>(psA, pqA, gamma_a, beta_a, scA, biA);
    k_bnrelu<<<(NN * 128 / 4) / 256, 256>>>(ya, scA, biA, c1);

    // conv_b and skip
    k_conv_mma<128, 27, false><<<NN / 128, 256, SMEM_CONV>>>(c1, neigh, wTb, yb);
    k_conv_mma<64, 1, true><<<NN / 128, 256, SMEM_SKIP>>>(xT, nullptr, wTs, ys);

    // BN stats
    k_reduce<<<256, 256>>>(yb, psB, pqB);
    k_finalize<<<1, 128>>>(psB, pqB, gamma_b, beta_b, scB, biB);
    k_reduce<<<256, 256>>>(ys, psS, pqS);
    k_finalize<<<1, 128>>>(psS, pqS, gamma_s, beta_s, scS, biS);

    // fused add + relu + transpose
    k_final<<<dim3(NN / 32, 4), dim3(32, 8)>>>(yb, ys, scB, biB, scS, biS, out);
}

// round 15
// speedup vs baseline: 2.3012x; 1.0129x over previous
#include <cuda_runtime.h>
#include <cstdint>

#define NN      65536
#define CIN_A   64
#define COUT    128
#define KK_A    27

// ---------------- scratch ----------------
__device__ float g_xT  [NN * CIN_A];            // x node-major [N][64], tf32-rounded
__device__ float g_wTa [KK_A * CIN_A * COUT];   // per-chunk [o][c] images (tf32)
__device__ float g_wTb [KK_A * COUT * COUT];
__device__ float g_wTs [CIN_A * COUT];
__device__ float g_ya  [NN * COUT];
__device__ float g_c1  [NN * COUT];             // tf32-rounded
__device__ float g_yb  [NN * COUT];
__device__ float g_ys  [NN * COUT];
__device__ float g_psumA[256 * 128], g_psqA[256 * 128];
__device__ float g_psumB[256 * 128], g_psqB[256 * 128];
__device__ float g_psumS[256 * 128], g_psqS[256 * 128];
__device__ float g_scA[128], g_biA[128];
__device__ float g_scB[128], g_biB[128];
__device__ float g_scS[128], g_biS[128];

// ---------------- helpers ----------------
__device__ __forceinline__ float to_tf32(float x) {
    uint32_t u;
    asm("cvt.rna.tf32.f32 %0, %1;" : "=r"(u) : "f"(x));
    return __uint_as_float(u);
}

__device__ __forceinline__ void cp16(uint32_t dst, const void* src) {
    asm volatile("cp.async.cg.shared.global [%0], [%1], 16;"
                 :: "r"(dst), "l"(src) : "memory");
}
#define CP_COMMIT() asm volatile("cp.async.commit_group;" ::: "memory")
#define CP_WAIT1()  asm volatile("cp.async.wait_group 1;" ::: "memory")
#define CP_WAIT0()  asm volatile("cp.async.wait_group 0;" ::: "memory")

// D += A(16x8,row) * B(8x8,col)  tf32 inputs, fp32 accum
__device__ __forceinline__ void mma8(float* d, const float* a, const float* b) {
    asm volatile(
        "mma.sync.aligned.m16n8k8.row.col.f32.tf32.tf32.f32 "
        "{%0,%1,%2,%3}, {%4,%5,%6,%7}, {%8,%9}, {%0,%1,%2,%3};"
        : "+f"(d[0]), "+f"(d[1]), "+f"(d[2]), "+f"(d[3])
        : "r"(__float_as_uint(a[0])), "r"(__float_as_uint(a[1])),
          "r"(__float_as_uint(a[2])), "r"(__float_as_uint(a[3])),
          "r"(__float_as_uint(b[0])), "r"(__float_as_uint(b[1])));
}

// ---------------- prep kernels ----------------

// data [64][N] -> xT [N][64], tf32-rounded
__global__ void k_transpose_x(const float* __restrict__ src, float* __restrict__ dst) {
    __shared__ float tile[32][33];
    int n0 = blockIdx.x * 32, c0 = blockIdx.y * 32;
    int tx = threadIdx.x, ty = threadIdx.y; // 32 x 8
    #pragma unroll
    for (int i = 0; i < 32; i += 8)
        tile[ty + i][tx] = src[(size_t)(c0 + ty + i) * NN + n0 + tx];
    __syncthreads();
    #pragma unroll
    for (int i = 0; i < 32; i += 8)
        dst[(size_t)(n0 + ty + i) * 64 + c0 + tx] = to_tf32(tile[tx][ty + i]);
}

// w [o][c][k] -> chunk images: wt[chunk][o*32 + (c%32)], chunk = k*(cin/32)+c/32
__global__ void k_wprep(const float* __restrict__ w, float* __restrict__ wt,
                        int cin, int kk) {
    int idx = blockIdx.x * blockDim.x + threadIdx.x;
    int total = COUT * cin * kk;
    if (idx >= total) return;
    int k = idx % kk;
    int c = (idx / kk) % cin;
    int o = idx / (kk * cin);
    int chunk = k * (cin >> 5) + (c >> 5);
    wt[(size_t)chunk * 4096 + o * 32 + (c & 31)] = to_tf32(w[idx]);
}

// ---------------- mma.sync implicit-GEMM conv (cp.async pipelined) ----------------
// y[n][o] = sum_{k,c} w[o][c][k] * src[neigh[n][k]][c]
// CTA: 128 nodes x 128 outs, 8 warps in 2(M) x 4(N), warp tile m64 n32.
// SMEM rows padded to 36 floats -> conflict-free fragment loads.
// 2-stage cp.async pipeline: loads for chunk q+1 overlap compute of chunk q.
template <int CIN, int KNB, bool SELF>
__global__ void __launch_bounds__(256, 2)
k_conv_mma(const float* __restrict__ src,   // [N][CIN] tf32
           const int*   __restrict__ nbr,   // [N][KNB] (unused if SELF)
           const float* __restrict__ wC,    // chunk images [Q][128*32]
           float*       __restrict__ y)     // [N][128]
{
    extern __shared__ char smem[];
    constexpr int NCH = CIN / 32;
    constexpr int Q   = KNB * NCH;
    constexpr int NBB = SELF ? 0 : 128 * KNB * 4;
    constexpr int OFF_A = (NBB + 15) & ~15;          // bytes
    constexpr int BUF   = 128 * 36;                  // floats per buffer
    // layout: [nb][A0][A1][B0][B1]

    int* nb = (int*)smem;
    float* Abase = (float*)(smem + OFF_A);
    float* Bbase = Abase + 2 * BUF;

    const int n0   = blockIdx.x * 128;
    const int t    = threadIdx.x;
    const int warp = t >> 5, lane = t & 31;
    const int wm   = warp & 1, wn = warp >> 1;
    const int r    = lane >> 2, cl = lane & 3;

    if (!SELF) {
        for (int i = t; i < 128 * KNB; i += 256)
            nb[i] = nbr[(size_t)n0 * KNB + i];
    }
    __syncthreads();

    float acc[4][4][4];
    #pragma unroll
    for (int i = 0; i < 4; ++i)
        #pragma unroll
        for (int j = 0; j < 4; ++j)
            #pragma unroll
            for (int e = 0; e < 4; ++e) acc[i][j][e] = 0.f;

    const int gnode = t >> 1, ghalf = t & 1;

    // issue async loads for chunk q into buffer q&1
    auto issue = [&](int q) {
        const int k  = q / NCH;
        const int cc = (q % NCH) * 32;
        float* As = Abase + (q & 1) * BUF;
        float* Bs = Bbase + (q & 1) * BUF;
        // A gather: this thread covers 16 floats of node gnode
        {
            int idx = SELF ? (n0 + gnode) : nb[gnode * KNB + k];
            const float* g = src + (size_t)idx * CIN + cc + ghalf * 16;
            uint32_t d = (uint32_t)__cvta_generic_to_shared(As + gnode * 36 + ghalf * 16);
            #pragma unroll
            for (int i = 0; i < 4; ++i)
                cp16(d + i * 16, g + i * 4);
        }
        // B copy: 1024 float4
        {
            const float* bsrc = wC + (size_t)q * 4096;
            #pragma unroll
            for (int i = 0; i < 4; ++i) {
                int p = t + 256 * i;
                uint32_t d = (uint32_t)__cvta_generic_to_shared(Bs + (p >> 3) * 36 + (p & 7) * 4);
                cp16(d, bsrc + p * 4);
            }
        }
        CP_COMMIT();
    };

    issue(0);

    for (int q = 0; q < Q; ++q) {
        if (q + 1 < Q) {
            issue(q + 1);   // overlaps with compute of chunk q
            CP_WAIT1();     // chunk q's group complete
        } else {
            CP_WAIT0();
        }
        __syncthreads();    // data visible to all warps

        float* As = Abase + (q & 1) * BUF;
        float* Bs = Bbase + (q & 1) * BUF;

        // compute: 4 k-steps of m16n8k8
        #pragma unroll
        for (int ks = 0; ks < 4; ++ks) {
            const int k0 = ks * 8;
            float a[4][4], b[4][2];
            #pragma unroll
            for (int i = 0; i < 4; ++i) {
                const float* base = As + (wm * 64 + i * 16 + r) * 36 + k0 + cl;
                a[i][0] = base[0];
                a[i][1] = base[8 * 36];
                a[i][2] = base[4];
                a[i][3] = base[8 * 36 + 4];
            }
            #pragma unroll
            for (int j = 0; j < 4; ++j) {
                const float* base = Bs + (wn * 32 + j * 8 + r) * 36 + k0 + cl;
                b[j][0] = base[0];
                b[j][1] = base[4];
            }
            #pragma unroll
            for (int i = 0; i < 4; ++i)
                #pragma unroll
                for (int j = 0; j < 4; ++j)
                    mma8(acc[i][j], a[i], b[j]);
        }
        __syncthreads();    // buffer q&1 free for issue at iteration q+1
    }

    // epilogue: d0,d1 at (row, 2c),(row, 2c+1); d2,d3 at (row+8, ...)
    #pragma unroll
    for (int i = 0; i < 4; ++i) {
        int row = n0 + wm * 64 + i * 16 + r;
        #pragma unroll
        for (int j = 0; j < 4; ++j) {
            int col = wn * 32 + j * 8 + cl * 2;
            *(float2*)(y + (size_t)row * 128 + col) =
                make_float2(acc[i][j][0], acc[i][j][1]);
            *(float2*)(y + (size_t)(row + 8) * 128 + col) =
                make_float2(acc[i][j][2], acc[i][j][3]);
        }
    }
}

// ---------------- BN stats (deterministic two-level) ----------------
__global__ void k_reduce(const float* __restrict__ y,
                         float* __restrict__ psum, float* __restrict__ psq) {
    int b = blockIdx.x, t = threadIdx.x;
    int c = t & 127, h = t >> 7;
    float s = 0.f, q = 0.f;
    const float* p = y + ((size_t)b * 256 + h * 128) * 128 + c;
    #pragma unroll 4
    for (int i = 0; i < 128; ++i) {
        float v = p[(size_t)i * 128];
        s += v;
        q += v * v;
    }
    __shared__ float sh[256], sh2[256];
    sh[t] = s; sh2[t] = q;
    __syncthreads();
    if (h == 0) {
        psum[b * 128 + c] = sh[c] + sh[128 + c];
        psq [b * 128 + c] = sh2[c] + sh2[128 + c];
    }
}

__global__ void k_finalize(const float* __restrict__ psum, const float* __restrict__ psq,
                           const float* __restrict__ gamma, const float* __restrict__ beta,
                           float* __restrict__ scale, float* __restrict__ bias) {
    int c = threadIdx.x; // 128
    double s = 0.0, q = 0.0;
    for (int i = 0; i < 256; ++i) {
        s += (double)psum[i * 128 + c];
        q += (double)psq [i * 128 + c];
    }
    double mu  = s / (double)NN;
    double var = q / (double)NN - mu * mu;
    float sc = gamma[c] * rsqrtf((float)var + 1e-3f);
    scale[c] = sc;
    bias[c]  = beta[c] - sc * (float)mu;
}

// c1 = tf32(relu(scale*y + bias))
__global__ void k_bnrelu(const float* __restrict__ y,
                         const float* __restrict__ scale, const float* __restrict__ bias,
                         float* __restrict__ c1) {
    size_t idx = (size_t)blockIdx.x * blockDim.x + threadIdx.x;
    float4 v = ((const float4*)y)[idx];
    int c = (int)((idx * 4) & 127);
    v.x = to_tf32(fmaxf(scale[c + 0] * v.x + bias[c + 0], 0.f));
    v.y = to_tf32(fmaxf(scale[c + 1] * v.y + bias[c + 1], 0.f));
    v.z = to_tf32(fmaxf(scale[c + 2] * v.z + bias[c + 2], 0.f));
    v.w = to_tf32(fmaxf(scale[c + 3] * v.w + bias[c + 3], 0.f));
    ((float4*)c1)[idx] = v;
}

// out[o][n] = relu(scB*yb[n][o]+biB + scS*ys[n][o]+biS)
__global__ void k_final(const float* __restrict__ yb, const float* __restrict__ ys,
                        const float* __restrict__ scB, const float* __restrict__ biB,
                        const float* __restrict__ scS, const float* __restrict__ biS,
                        float* __restrict__ out) {
    __shared__ float tile[32][33];
    int n0 = blockIdx.x * 32, o0 = blockIdx.y * 32;
    int tx = threadIdx.x, ty = threadIdx.y; // 32 x 8
    #pragma unroll
    for (int i = 0; i < 32; i += 8) {
        int n = n0 + ty + i, o = o0 + tx;
        size_t off = (size_t)n * 128 + o;
        float v = scB[o] * yb[off] + biB[o] + scS[o] * ys[off] + biS[o];
        tile[ty + i][tx] = fmaxf(v, 0.f);
    }
    __syncthreads();
    #pragma unroll
    for (int i = 0; i < 32; i += 8)
        out[(size_t)(o0 + ty + i) * NN + n0 + tx] = tile[tx][ty + i];
}

// ---------------- launch ----------------
template <typename T>
static T* sym_addr(const void* sym) {
    void* p = nullptr;
    cudaGetSymbolAddress(&p, sym);
    return (T*)p;
}

// conv smem: nb(128*27*4=13824, 16B-aligned) + 4 bufs * 18432 = 87552
// skip smem: 4 bufs * 18432 = 73728
enum { SMEM_CONV = 87552, SMEM_SKIP = 73728 };

extern "C" void kernel_launch(void* const* d_in, const int* in_sizes, int n_in,
                              void* d_out, int out_size) {
    const float* data    = (const float*)d_in[0];
    const int*   neigh   = (const int*)  d_in[1];
    const float* w_a     = (const float*)d_in[2];
    const float* w_b     = (const float*)d_in[3];
    const float* w_skip  = (const float*)d_in[4];
    const float* gamma_a = (const float*)d_in[5];
    const float* beta_a  = (const float*)d_in[6];
    const float* gamma_b = (const float*)d_in[7];
    const float* beta_b  = (const float*)d_in[8];
    const float* gamma_s = (const float*)d_in[9];
    const float* beta_s  = (const float*)d_in[10];
    float* out = (float*)d_out;

    float* xT  = sym_addr<float>(g_xT);
    float* wTa = sym_addr<float>(g_wTa);
    float* wTb = sym_addr<float>(g_wTb);
    float* wTs = sym_addr<float>(g_wTs);
    float* ya  = sym_addr<float>(g_ya);
    float* c1  = sym_addr<float>(g_c1);
    float* yb  = sym_addr<float>(g_yb);
    float* ys  = sym_addr<float>(g_ys);
    float* psA = sym_addr<float>(g_psumA); float* pqA = sym_addr<float>(g_psqA);
    float* psB = sym_addr<float>(g_psumB); float* pqB = sym_addr<float>(g_psqB);
    float* psS = sym_addr<float>(g_psumS); float* pqS = sym_addr<float>(g_psqS);
    float* scA = sym_addr<float>(g_scA);   float* biA = sym_addr<float>(g_biA);
    float* scB = sym_addr<float>(g_scB);   float* biB = sym_addr<float>(g_biB);
    float* scS = sym_addr<float>(g_scS);   float* biS = sym_addr<float>(g_biS);

    cudaFuncSetAttribute(k_conv_mma<64, 27, false>,
                         cudaFuncAttributeMaxDynamicSharedMemorySize, SMEM_CONV);
    cudaFuncSetAttribute(k_conv_mma<128, 27, false>,
                         cudaFuncAttributeMaxDynamicSharedMemorySize, SMEM_CONV);
    cudaFuncSetAttribute(k_conv_mma<64, 1, true>,
                         cudaFuncAttributeMaxDynamicSharedMemorySize, SMEM_SKIP);

    // prep
    k_transpose_x<<<dim3(NN / 32, 2), dim3(32, 8)>>>(data, xT);
    k_wprep<<<(COUT * CIN_A * KK_A + 255) / 256, 256>>>(w_a, wTa, CIN_A, KK_A);
    k_wprep<<<(COUT * COUT * KK_A + 255) / 256, 256>>>(w_b, wTb, COUT, KK_A);
    k_wprep<<<(COUT * CIN_A + 255) / 256, 256>>>(w_skip, wTs, CIN_A, 1);

    // conv_a -> BN -> relu
    k_conv_mma<64, 27, false><<<NN / 128, 256, SMEM_CONV>>>(xT, neigh, wTa, ya);
    k_reduce<<<256, 256>>>(ya, psA, pqA);
    k_finalize<<<1, 128>>>(psA, pqA, gamma_a, beta_a, scA, biA);
    k_bnrelu<<<(NN * 128 / 4) / 256, 256>>>(ya, scA, biA, c1);

    // conv_b and skip
    k_conv_mma<128, 27, false><<<NN / 128, 256, SMEM_CONV>>>(c1, neigh, wTb, yb);
    k_conv_mma<64, 1, true><<<NN / 128, 256, SMEM_SKIP>>>(xT, nullptr, wTs, ys);

    // BN stats
    k_reduce<<<256, 256>>>(yb, psB, pqB);
    k_finalize<<<1, 128>>>(psB, pqB, gamma_b, beta_b, scB, biB);
    k_reduce<<<256, 256>>>(ys, psS, pqS);
    k_finalize<<<1, 128>>>(psS, pqS, gamma_s, beta_s, scS, biS);

    // fused add + relu + transpose
    k_final<<<dim3(NN / 32, 4), dim3(32, 8)>>>(yb, ys, scB, biB, scS, biS, out);
}